// round 2
// baseline (speedup 1.0000x reference)
#include <cuda_runtime.h>
#include <math.h>

#define B_ 1024
#define S_ 256
#define D_ 128
#define H_ 512
#define G4_ 2048   // 4*H
#define KA_ 768    // packed A width: [x_c(128) | m(128) | hd(512)]

// ---------------- static device scratch (no allocations allowed) ----------------
__device__ float g_h[B_*H_];
__device__ float g_c[B_*H_];
__device__ float g_A[B_*KA_];        // packed activations per step
__device__ float g_gates[B_*G4_];
__device__ float g_xf[B_*S_*D_];     // precomputed feat_reg(x) for all (b,s)
__device__ float g_WgT[KA_*G4_];     // k-major combined [Wih_x|Wih_m|Whh]
__device__ float g_WhrT[H_*D_];      // k-major Whr
__device__ float g_WfrT[D_*D_];      // k-major Wfr
__device__ float g_wd[G4_];          // Wih[:,256] (delta column)
__device__ float g_bias[G4_];        // bih + bhh
__device__ float g_lnum[S_];
__device__ float g_lden[S_];

// ---------------- init: zero state + loss accumulators ----------------
__global__ void k_init() {
    int n = 2*B_*H_ + 2*S_;
    for (int i = blockIdx.x*blockDim.x + threadIdx.x; i < n; i += gridDim.x*blockDim.x) {
        if (i < B_*H_) g_h[i] = 0.f;
        else if (i < 2*B_*H_) g_c[i - B_*H_] = 0.f;
        else {
            int j = i - 2*B_*H_;
            if (j < S_) g_lnum[j] = 0.f; else g_lden[j - S_] = 0.f;
        }
    }
}

// ---------------- build transposed/packed weights ----------------
__global__ void k_weights(const float* __restrict__ Wih, const float* __restrict__ Whh,
                          const float* __restrict__ Whr, const float* __restrict__ Wfr,
                          const float* __restrict__ bih, const float* __restrict__ bhh) {
    const int N1 = KA_*G4_;
    const int N2 = N1 + H_*D_;
    const int N3 = N2 + D_*D_;
    const int N4 = N3 + G4_;
    const int N5 = N4 + G4_;
    for (int i = blockIdx.x*blockDim.x + threadIdx.x; i < N5; i += gridDim.x*blockDim.x) {
        if (i < N1) {
            int k = i >> 11, g = i & (G4_-1);
            g_WgT[i] = (k < 256) ? Wih[g*257 + k] : Whh[g*H_ + (k-256)];
        } else if (i < N2) {
            int t = i - N1; int j = t >> 7, c = t & 127;
            g_WhrT[t] = Whr[c*H_ + j];
        } else if (i < N3) {
            int t = i - N2; int k = t >> 7, c = t & 127;
            g_WfrT[t] = Wfr[c*D_ + k];
        } else if (i < N4) {
            int g = i - N3;
            g_wd[g] = Wih[g*257 + 256];
        } else {
            int g = i - N4;
            g_bias[g] = bih[g] + bhh[g];
        }
    }
}

// ---------------- precompute x_f = data @ Wfr^T + bfr for all (b,s) ----------------
__global__ __launch_bounds__(256) void k_xf(const float* __restrict__ data,
                                            const float* __restrict__ bfr) {
    __shared__ float xs[32][128];
    int row0 = blockIdx.x * 32;   // row = b*S_+s
    for (int idx = threadIdx.x; idx < 32*128; idx += 256)
        xs[idx >> 7][idx & 127] = data[row0*128 + idx];
    __syncthreads();

    int rg = threadIdx.x >> 5;          // 0..7
    int c  = (threadIdx.x & 31) << 2;   // 0..124 step 4
    float4 acc[4];
    #pragma unroll
    for (int rr = 0; rr < 4; rr++) acc[rr] = make_float4(0.f,0.f,0.f,0.f);

    #pragma unroll 4
    for (int k = 0; k < 128; k++) {
        float4 w = *(const float4*)(g_WfrT + k*D_ + c);
        #pragma unroll
        for (int rr = 0; rr < 4; rr++) {
            float a = xs[rg + rr*8][k];
            acc[rr].x = fmaf(a, w.x, acc[rr].x);
            acc[rr].y = fmaf(a, w.y, acc[rr].y);
            acc[rr].z = fmaf(a, w.z, acc[rr].z);
            acc[rr].w = fmaf(a, w.w, acc[rr].w);
        }
    }
    float4 bb = *(const float4*)(bfr + c);
    #pragma unroll
    for (int rr = 0; rr < 4; rr++) {
        int r = row0 + rg + rr*8;
        float4 o;
        o.x = acc[rr].x + bb.x; o.y = acc[rr].y + bb.y;
        o.z = acc[rr].z + bb.z; o.w = acc[rr].w + bb.w;
        *(float4*)(g_xf + r*D_ + c) = o;
    }
}

// ---------------- per-step: decay + x_h GEMM + pack A ----------------
__global__ __launch_bounds__(256) void k_pre(const float* __restrict__ data,
                                             const float* __restrict__ masks,
                                             const float* __restrict__ deltas,
                                             const float* __restrict__ Wtd,
                                             const float* __restrict__ btd,
                                             const float* __restrict__ bhr, int s) {
    __shared__ float hd[8][H_];
    int b0 = blockIdx.x * 8;
    for (int idx = threadIdx.x; idx < 8*H_; idx += 256) {
        int r = idx >> 9, j = idx & 511;
        int b = b0 + r;
        float dv = deltas[b*S_ + s];
        float e = expf(-fmaxf(fmaf(dv, Wtd[j], btd[j]), 0.f));
        float v = g_h[b*H_ + j] * e;
        hd[r][j] = v;
        g_A[b*KA_ + 256 + j] = v;
    }
    __syncthreads();

    int r = threadIdx.x >> 5;
    int c = (threadIdx.x & 31) << 2;
    float4 acc = make_float4(0.f,0.f,0.f,0.f);
    #pragma unroll 8
    for (int k = 0; k < H_; k++) {
        float a = hd[r][k];
        float4 w = *(const float4*)(g_WhrT + k*D_ + c);
        acc.x = fmaf(a, w.x, acc.x);
        acc.y = fmaf(a, w.y, acc.y);
        acc.z = fmaf(a, w.z, acc.z);
        acc.w = fmaf(a, w.w, acc.w);
    }
    int b = b0 + r;
    int base = (b*S_ + s)*D_ + c;
    float4 bh = *(const float4*)(bhr + c);
    float4 xv = *(const float4*)(data + base);
    float4 mv = *(const float4*)(masks + base);
    float4 xc;
    xc.x = mv.x*xv.x + (1.f-mv.x)*(acc.x + bh.x);
    xc.y = mv.y*xv.y + (1.f-mv.y)*(acc.y + bh.y);
    xc.z = mv.z*xv.z + (1.f-mv.z)*(acc.z + bh.z);
    xc.w = mv.w*xv.w + (1.f-mv.w)*(acc.w + bh.w);
    *(float4*)(g_A + b*KA_ + c)       = xc;
    *(float4*)(g_A + b*KA_ + 128 + c) = mv;
}

// ---------------- per-step: gates SGEMM [1024x768]@[768x2048] ----------------
__global__ __launch_bounds__(256) void k_gates(int s, const float* __restrict__ deltas) {
    __shared__ float As[2][16*128];   // transposed: As[k][row]
    __shared__ float Bs[2][16*128];   // Bs[k][col]
    int tid = threadIdx.x;
    int bm = blockIdx.y * 128;
    int bn = blockIdx.x * 128;

    int arow = tid >> 1;             // 0..127
    int acol = (tid & 1) << 3;       // 0 or 8
    int brow = tid >> 5;             // 0..7
    int bcol = (tid & 31) << 2;      // 0..124

    int ty = tid >> 4;               // 0..15 (row micro-tile)
    int tx = tid & 15;               // 0..15 (col micro-tile)

    float acc[8][8];
    #pragma unroll
    for (int i = 0; i < 8; i++)
        #pragma unroll
        for (int j = 0; j < 8; j++) acc[i][j] = 0.f;

    // load tile 0
    {
        float4 ra0 = *(const float4*)(g_A + (bm+arow)*KA_ + acol);
        float4 ra1 = *(const float4*)(g_A + (bm+arow)*KA_ + acol + 4);
        float4 rb0 = *(const float4*)(g_WgT + (brow)*G4_ + bn + bcol);
        float4 rb1 = *(const float4*)(g_WgT + (brow+8)*G4_ + bn + bcol);
        As[0][(acol+0)*128 + arow] = ra0.x;
        As[0][(acol+1)*128 + arow] = ra0.y;
        As[0][(acol+2)*128 + arow] = ra0.z;
        As[0][(acol+3)*128 + arow] = ra0.w;
        As[0][(acol+4)*128 + arow] = ra1.x;
        As[0][(acol+5)*128 + arow] = ra1.y;
        As[0][(acol+6)*128 + arow] = ra1.z;
        As[0][(acol+7)*128 + arow] = ra1.w;
        *(float4*)&Bs[0][brow*128 + bcol]     = rb0;
        *(float4*)&Bs[0][(brow+8)*128 + bcol] = rb1;
    }
    __syncthreads();

    int buf = 0;
    for (int kt = 0; kt < 48; kt++) {
        float4 ra0, ra1, rb0, rb1;
        if (kt < 47) {
            int k0 = (kt+1)*16;
            ra0 = *(const float4*)(g_A + (bm+arow)*KA_ + k0 + acol);
            ra1 = *(const float4*)(g_A + (bm+arow)*KA_ + k0 + acol + 4);
            rb0 = *(const float4*)(g_WgT + (k0+brow)*G4_ + bn + bcol);
            rb1 = *(const float4*)(g_WgT + (k0+brow+8)*G4_ + bn + bcol);
        }
        #pragma unroll
        for (int kk = 0; kk < 16; kk++) {
            float a[8], b[8];
            *(float4*)(a)   = *(float4*)&As[buf][kk*128 + ty*8];
            *(float4*)(a+4) = *(float4*)&As[buf][kk*128 + ty*8 + 4];
            *(float4*)(b)   = *(float4*)&Bs[buf][kk*128 + tx*8];
            *(float4*)(b+4) = *(float4*)&Bs[buf][kk*128 + tx*8 + 4];
            #pragma unroll
            for (int i = 0; i < 8; i++)
                #pragma unroll
                for (int j = 0; j < 8; j++)
                    acc[i][j] = fmaf(a[i], b[j], acc[i][j]);
        }
        if (kt < 47) {
            int nb = buf ^ 1;
            As[nb][(acol+0)*128 + arow] = ra0.x;
            As[nb][(acol+1)*128 + arow] = ra0.y;
            As[nb][(acol+2)*128 + arow] = ra0.z;
            As[nb][(acol+3)*128 + arow] = ra0.w;
            As[nb][(acol+4)*128 + arow] = ra1.x;
            As[nb][(acol+5)*128 + arow] = ra1.y;
            As[nb][(acol+6)*128 + arow] = ra1.z;
            As[nb][(acol+7)*128 + arow] = ra1.w;
            *(float4*)&Bs[nb][brow*128 + bcol]     = rb0;
            *(float4*)&Bs[nb][(brow+8)*128 + bcol] = rb1;
            __syncthreads();
            buf = nb;
        }
    }

    // epilogue: + delta*wd + (bih+bhh)
    #pragma unroll
    for (int i = 0; i < 8; i++) {
        int rowb = bm + ty*8 + i;
        float dv = deltas[rowb*S_ + s];
        #pragma unroll
        for (int jj = 0; jj < 2; jj++) {
            int col = bn + tx*8 + jj*4;
            float4 wd4 = *(const float4*)(g_wd + col);
            float4 bi4 = *(const float4*)(g_bias + col);
            float4 o;
            o.x = acc[i][jj*4+0] + dv*wd4.x + bi4.x;
            o.y = acc[i][jj*4+1] + dv*wd4.y + bi4.y;
            o.z = acc[i][jj*4+2] + dv*wd4.z + bi4.z;
            o.w = acc[i][jj*4+3] + dv*wd4.w + bi4.w;
            *(float4*)(g_gates + rowb*G4_ + col) = o;
        }
    }
}

// ---------------- per-step: LSTM pointwise + x_h2 GEMM + output + loss ----------------
__global__ __launch_bounds__(256) void k_post(const float* __restrict__ data,
                                              const float* __restrict__ masks,
                                              const float* __restrict__ bhr,
                                              int s, float* __restrict__ out) {
    __shared__ float hs[8][H_];
    __shared__ float red[16];
    int b0 = blockIdx.x * 8;

    for (int idx = threadIdx.x; idx < 8*H_; idx += 256) {
        int r = idx >> 9, j = idx & 511;
        int b = b0 + r;
        const float* gr = g_gates + b*G4_;
        float gi = gr[j];
        float gf = gr[H_   + j];
        float gg = gr[2*H_ + j];
        float go = gr[3*H_ + j];
        float ig = 1.f/(1.f + expf(-gi));
        float fg = 1.f/(1.f + expf(-gf));
        float gt = tanhf(gg);
        float og = 1.f/(1.f + expf(-go));
        float cn = fg * g_c[b*H_ + j] + ig * gt;
        float hn = og * tanhf(cn);
        g_c[b*H_ + j] = cn;
        g_h[b*H_ + j] = hn;
        hs[r][j] = hn;
    }
    __syncthreads();

    int r = threadIdx.x >> 5;
    int c = (threadIdx.x & 31) << 2;
    float4 acc = make_float4(0.f,0.f,0.f,0.f);
    #pragma unroll 8
    for (int k = 0; k < H_; k++) {
        float a = hs[r][k];
        float4 w = *(const float4*)(g_WhrT + k*D_ + c);
        acc.x = fmaf(a, w.x, acc.x);
        acc.y = fmaf(a, w.y, acc.y);
        acc.z = fmaf(a, w.z, acc.z);
        acc.w = fmaf(a, w.w, acc.w);
    }
    int b = b0 + r;
    int base = (b*S_ + s)*D_ + c;
    float4 bh  = *(const float4*)(bhr + c);
    float4 xv  = *(const float4*)(data + base);
    float4 mv  = *(const float4*)(masks + base);
    float4 xfv = *(const float4*)(g_xf + base);
    float4 xh2;
    xh2.x = acc.x + bh.x; xh2.y = acc.y + bh.y;
    xh2.z = acc.z + bh.z; xh2.w = acc.w + bh.w;
    float4 o;
    o.x = mv.x*xv.x + (1.f-mv.x)*(xh2.x + xfv.x);
    o.y = mv.y*xv.y + (1.f-mv.y)*(xh2.y + xfv.y);
    o.z = mv.z*xv.z + (1.f-mv.z)*(xh2.z + xfv.z);
    o.w = mv.w*xv.w + (1.f-mv.w)*(xh2.w + xfv.w);
    *(float4*)(out + base) = o;

    float ex = xv.x - xh2.x, ey = xv.y - xh2.y, ez = xv.z - xh2.z, ew = xv.w - xh2.w;
    float ln = mv.x*ex*ex + mv.y*ey*ey + mv.z*ez*ez + mv.w*ew*ew;
    float ld = mv.x + mv.y + mv.z + mv.w;
    #pragma unroll
    for (int off = 16; off > 0; off >>= 1) {
        ln += __shfl_down_sync(0xffffffffu, ln, off);
        ld += __shfl_down_sync(0xffffffffu, ld, off);
    }
    int warp = threadIdx.x >> 5;
    if ((threadIdx.x & 31) == 0) { red[2*warp] = ln; red[2*warp+1] = ld; }
    __syncthreads();
    if (threadIdx.x == 0) {
        float a = 0.f, d2 = 0.f;
        #pragma unroll
        for (int w = 0; w < 8; w++) { a += red[2*w]; d2 += red[2*w+1]; }
        atomicAdd(&g_lnum[s], a);
        atomicAdd(&g_lden[s], d2);
    }
}

// ---------------- final loss ----------------
__global__ void k_loss(float* __restrict__ out, long long out_size) {
    __shared__ float sh[256];
    int t = threadIdx.x;
    sh[t] = g_lnum[t] / (g_lden[t] + 1e-5f);
    __syncthreads();
    for (int off = 128; off > 0; off >>= 1) {
        if (t < off) sh[t] += sh[t + off];
        __syncthreads();
    }
    if (t == 0 && out_size > (long long)B_*S_*D_)
        out[(long long)B_*S_*D_] = sh[0] / (float)S_;
}

// ---------------- launch ----------------
extern "C" void kernel_launch(void* const* d_in, const int* in_sizes, int n_in,
                              void* d_out, int out_size) {
    const float* data   = (const float*)d_in[0];
    const float* masks  = (const float*)d_in[1];
    const float* deltas = (const float*)d_in[2];
    const float* Wih    = (const float*)d_in[3];
    const float* Whh    = (const float*)d_in[4];
    const float* bih    = (const float*)d_in[5];
    const float* bhh    = (const float*)d_in[6];
    const float* Wtd    = (const float*)d_in[7];
    const float* btd    = (const float*)d_in[8];
    const float* Whr    = (const float*)d_in[9];
    const float* bhr    = (const float*)d_in[10];
    const float* Wfr    = (const float*)d_in[11];
    const float* bfr    = (const float*)d_in[12];
    float* out = (float*)d_out;

    k_init<<<1024, 256>>>();
    k_weights<<<2048, 256>>>(Wih, Whh, Whr, Wfr, bih, bhh);
    k_xf<<<(B_*S_)/32, 256>>>(data, bfr);

    for (int s = 0; s < S_; s++) {
        k_pre<<<B_/8, 256>>>(data, masks, deltas, Wtd, btd, bhr, s);
        k_gates<<<dim3(G4_/128, B_/128), 256>>>(s, deltas);
        k_post<<<B_/8, 256>>>(data, masks, bhr, s, out);
    }
    k_loss<<<1, 256>>>(out, (long long)out_size);
}

// round 4
// speedup vs baseline: 1.2591x; 1.2591x over previous
#include <cuda_runtime.h>
#include <math.h>

#define B_ 1024
#define S_ 256
#define D_ 128
#define H_ 512
#define G4_ 2048   // 4*H
#define KA_ 768    // logical A width: [x_c(128) | m(128) | hd(512)]

// ---------------- static device scratch (no allocations allowed) ----------------
__device__ float g_h[B_*H_];
__device__ float g_c[B_*H_];
__device__ float g_hd[B_*H_];          // decayed h for current step
__device__ float g_xc[B_*D_];          // x_c for current step
__device__ float g_gates[B_*G4_];
__device__ float g_xf[B_*S_*D_];       // precomputed feat_reg(x) for all (b,s)
__device__ float g_WgT[KA_*G4_];       // k-major combined [Wih_x|Wih_m|Whh]
__device__ float g_WhrT[H_*D_];        // k-major Whr
__device__ float g_WfrT[D_*D_];        // k-major Wfr
__device__ float g_wd[G4_];            // Wih[:,256] (delta column)
__device__ float g_bias[G4_];          // bih + bhh
__device__ float g_bhr[D_];
__device__ float g_lnum[S_];
__device__ float g_lden[S_];

// ---------------- init: zero state + loss accumulators ----------------
__global__ void k_init() {
    int n = 2*B_*H_ + 2*S_;
    for (int i = blockIdx.x*blockDim.x + threadIdx.x; i < n; i += gridDim.x*blockDim.x) {
        if (i < B_*H_) g_h[i] = 0.f;
        else if (i < 2*B_*H_) g_c[i - B_*H_] = 0.f;
        else {
            int j = i - 2*B_*H_;
            if (j < S_) g_lnum[j] = 0.f; else g_lden[j - S_] = 0.f;
        }
    }
}

// ---------------- build transposed/packed weights ----------------
__global__ void k_weights(const float* __restrict__ Wih, const float* __restrict__ Whh,
                          const float* __restrict__ Whr, const float* __restrict__ Wfr,
                          const float* __restrict__ bih, const float* __restrict__ bhh,
                          const float* __restrict__ bhr) {
    const int N1 = KA_*G4_;
    const int N2 = N1 + H_*D_;
    const int N3 = N2 + D_*D_;
    const int N4 = N3 + G4_;
    const int N5 = N4 + G4_;
    const int N6 = N5 + D_;
    for (int i = blockIdx.x*blockDim.x + threadIdx.x; i < N6; i += gridDim.x*blockDim.x) {
        if (i < N1) {
            int k = i >> 11, g = i & (G4_-1);
            g_WgT[i] = (k < 256) ? Wih[g*257 + k] : Whh[g*H_ + (k-256)];
        } else if (i < N2) {
            int t = i - N1; int j = t >> 7, c = t & 127;
            g_WhrT[t] = Whr[c*H_ + j];
        } else if (i < N3) {
            int t = i - N2; int k = t >> 7, c = t & 127;
            g_WfrT[t] = Wfr[c*D_ + k];
        } else if (i < N4) {
            int g = i - N3;
            g_wd[g] = Wih[g*257 + 256];
        } else if (i < N5) {
            int g = i - N4;
            g_bias[g] = bih[g] + bhh[g];
        } else {
            int c = i - N5;
            g_bhr[c] = bhr[c];
        }
    }
}

// ---------------- precompute x_f = data @ Wfr^T + bfr for all (b,s) ----------------
__global__ __launch_bounds__(256) void k_xf(const float* __restrict__ data,
                                            const float* __restrict__ bfr) {
    __shared__ float xs[32][128];
    int row0 = blockIdx.x * 32;   // row = b*S_+s
    for (int idx = threadIdx.x; idx < 32*128; idx += 256)
        xs[idx >> 7][idx & 127] = data[row0*128 + idx];
    __syncthreads();

    int rg = threadIdx.x >> 5;          // 0..7
    int c  = (threadIdx.x & 31) << 2;   // 0..124 step 4
    float4 acc[4];
    #pragma unroll
    for (int rr = 0; rr < 4; rr++) acc[rr] = make_float4(0.f,0.f,0.f,0.f);

    #pragma unroll 4
    for (int k = 0; k < 128; k++) {
        float4 w = *(const float4*)(g_WfrT + k*D_ + c);
        #pragma unroll
        for (int rr = 0; rr < 4; rr++) {
            float a = xs[rg + rr*8][k];
            acc[rr].x = fmaf(a, w.x, acc[rr].x);
            acc[rr].y = fmaf(a, w.y, acc[rr].y);
            acc[rr].z = fmaf(a, w.z, acc[rr].z);
            acc[rr].w = fmaf(a, w.w, acc[rr].w);
        }
    }
    float4 bb = *(const float4*)(bfr + c);
    #pragma unroll
    for (int rr = 0; rr < 4; rr++) {
        int r = row0 + rg + rr*8;
        float4 o;
        o.x = acc[rr].x + bb.x; o.y = acc[rr].y + bb.y;
        o.z = acc[rr].z + bb.z; o.w = acc[rr].w + bb.w;
        *(float4*)(g_xf + r*D_ + c) = o;
    }
}

// ---------------- per-step: decay + hd@WhrT (K=512, smem-staged W) + x_c ----------------
// grid 128 blocks (8 rows each), 256 threads
__global__ __launch_bounds__(256) void k_pre(const float* __restrict__ data,
                                             const float* __restrict__ masks,
                                             const float* __restrict__ deltas,
                                             const float* __restrict__ Wtd,
                                             const float* __restrict__ btd, int s) {
    __shared__ float hd_s[8][H_];      // 16 KB
    __shared__ float Ws[32][128];      // 16 KB
    int rb = blockIdx.x;
    int tid = threadIdx.x;

    // phase 1: decayed h (8 rows x 512)
    #pragma unroll
    for (int t = 0; t < 16; t++) {
        int idx = tid + t*256;
        int r = idx >> 9, j = idx & 511;
        int b = rb*8 + r;
        float dv = deltas[b*S_ + s];
        float e = expf(-fmaxf(fmaf(dv, Wtd[j], btd[j]), 0.f));
        float v = g_h[b*H_ + j] * e;
        hd_s[r][j] = v;
        g_hd[b*H_ + j] = v;
    }
    __syncthreads();

    // phase 2: 8x128 GEMM over K=512, W staged in 32-row chunks
    int r = tid >> 5;
    int c4 = (tid & 31) << 2;
    float4 acc = make_float4(0.f,0.f,0.f,0.f);
    for (int kc = 0; kc < H_; kc += 32) {
        #pragma unroll
        for (int i = 0; i < 4; i++) {
            int lidx = tid + i*256;          // 1024 float4s
            int kr = lidx >> 5, cc = (lidx & 31) << 2;
            *(float4*)&Ws[kr][cc] = *(const float4*)(g_WhrT + (kc + kr)*D_ + cc);
        }
        __syncthreads();
        #pragma unroll 8
        for (int k = 0; k < 32; k++) {
            float a = hd_s[r][kc + k];
            float4 w = *(const float4*)&Ws[k][c4];
            acc.x = fmaf(a, w.x, acc.x);
            acc.y = fmaf(a, w.y, acc.y);
            acc.z = fmaf(a, w.z, acc.z);
            acc.w = fmaf(a, w.w, acc.w);
        }
        __syncthreads();
    }

    // epilogue: x_c = m*x + (1-m)*(x_h + bhr)
    int b = rb*8 + r;
    int base = (b*S_ + s)*D_ + c4;
    float4 bh = *(const float4*)(g_bhr + c4);
    float4 xv = *(const float4*)(data + base);
    float4 mv = *(const float4*)(masks + base);
    float4 xc;
    xc.x = mv.x*xv.x + (1.f-mv.x)*(acc.x + bh.x);
    xc.y = mv.y*xv.y + (1.f-mv.y)*(acc.y + bh.y);
    xc.z = mv.z*xv.z + (1.f-mv.z)*(acc.z + bh.z);
    xc.w = mv.w*xv.w + (1.f-mv.w)*(acc.w + bh.w);
    *(float4*)(g_xc + b*D_ + c4) = xc;
}

// ---------------- gates A-tile element loader (8 consecutive k at [row]) ----------------
__device__ __forceinline__ void fillA(int row, int k, int s,
                                      const float* __restrict__ masks,
                                      float4& lo, float4& hi) {
    if (k >= 256) {
        const float* p = g_hd + row*H_ + (k - 256);
        lo = *(const float4*)p;
        hi = *(const float4*)(p + 4);
    } else if (k >= 128) {
        const float* p = masks + (row*S_ + s)*D_ + (k - 128);
        lo = *(const float4*)p;
        hi = *(const float4*)(p + 4);
    } else {
        const float* p = g_xc + row*D_ + k;
        lo = *(const float4*)p;
        hi = *(const float4*)(p + 4);
    }
}

// ---------------- per-step: gates SGEMM [1024x768]@[768x2048] ----------------
__global__ __launch_bounds__(256) void k_gates(int s, const float* __restrict__ deltas,
                                               const float* __restrict__ masks) {
    __shared__ float As[2][16*128];   // transposed: As[k][row]
    __shared__ float Bs[2][16*128];   // Bs[k][col]
    int tid = threadIdx.x;
    int bm = blockIdx.y * 128;
    int bn = blockIdx.x * 128;

    int arow = tid >> 1;             // 0..127
    int acol = (tid & 1) << 3;       // 0 or 8
    int brow = tid >> 5;             // 0..7
    int bcol = (tid & 31) << 2;      // 0..124

    int ty = tid >> 4;               // 0..15 (row micro-tile)
    int tx = tid & 15;               // 0..15 (col micro-tile)

    float acc[8][8];
    #pragma unroll
    for (int i = 0; i < 8; i++)
        #pragma unroll
        for (int j = 0; j < 8; j++) acc[i][j] = 0.f;

    // load tile 0
    {
        float4 ra0, ra1;
        fillA(bm + arow, acol, s, masks, ra0, ra1);
        float4 rb0 = *(const float4*)(g_WgT + (brow)*G4_ + bn + bcol);
        float4 rb1 = *(const float4*)(g_WgT + (brow+8)*G4_ + bn + bcol);
        As[0][(acol+0)*128 + arow] = ra0.x;
        As[0][(acol+1)*128 + arow] = ra0.y;
        As[0][(acol+2)*128 + arow] = ra0.z;
        As[0][(acol+3)*128 + arow] = ra0.w;
        As[0][(acol+4)*128 + arow] = ra1.x;
        As[0][(acol+5)*128 + arow] = ra1.y;
        As[0][(acol+6)*128 + arow] = ra1.z;
        As[0][(acol+7)*128 + arow] = ra1.w;
        *(float4*)&Bs[0][brow*128 + bcol]     = rb0;
        *(float4*)&Bs[0][(brow+8)*128 + bcol] = rb1;
    }
    __syncthreads();

    int buf = 0;
    for (int kt = 0; kt < 48; kt++) {
        float4 ra0, ra1, rb0, rb1;
        if (kt < 47) {
            int k0 = (kt+1)*16;
            fillA(bm + arow, k0 + acol, s, masks, ra0, ra1);
            rb0 = *(const float4*)(g_WgT + (k0+brow)*G4_ + bn + bcol);
            rb1 = *(const float4*)(g_WgT + (k0+brow+8)*G4_ + bn + bcol);
        }
        #pragma unroll
        for (int kk = 0; kk < 16; kk++) {
            float a[8], b[8];
            *(float4*)(a)   = *(float4*)&As[buf][kk*128 + ty*8];
            *(float4*)(a+4) = *(float4*)&As[buf][kk*128 + ty*8 + 4];
            *(float4*)(b)   = *(float4*)&Bs[buf][kk*128 + tx*8];
            *(float4*)(b+4) = *(float4*)&Bs[buf][kk*128 + tx*8 + 4];
            #pragma unroll
            for (int i = 0; i < 8; i++)
                #pragma unroll
                for (int j = 0; j < 8; j++)
                    acc[i][j] = fmaf(a[i], b[j], acc[i][j]);
        }
        if (kt < 47) {
            int nb = buf ^ 1;
            As[nb][(acol+0)*128 + arow] = ra0.x;
            As[nb][(acol+1)*128 + arow] = ra0.y;
            As[nb][(acol+2)*128 + arow] = ra0.z;
            As[nb][(acol+3)*128 + arow] = ra0.w;
            As[nb][(acol+4)*128 + arow] = ra1.x;
            As[nb][(acol+5)*128 + arow] = ra1.y;
            As[nb][(acol+6)*128 + arow] = ra1.z;
            As[nb][(acol+7)*128 + arow] = ra1.w;
            *(float4*)&Bs[nb][brow*128 + bcol]     = rb0;
            *(float4*)&Bs[nb][(brow+8)*128 + bcol] = rb1;
            __syncthreads();
            buf = nb;
        }
    }

    // epilogue: + delta*wd + (bih+bhh)
    #pragma unroll
    for (int i = 0; i < 8; i++) {
        int rowb = bm + ty*8 + i;
        float dv = deltas[rowb*S_ + s];
        #pragma unroll
        for (int jj = 0; jj < 2; jj++) {
            int col = bn + tx*8 + jj*4;
            float4 wd4 = *(const float4*)(g_wd + col);
            float4 bi4 = *(const float4*)(g_bias + col);
            float4 o;
            o.x = acc[i][jj*4+0] + dv*wd4.x + bi4.x;
            o.y = acc[i][jj*4+1] + dv*wd4.y + bi4.y;
            o.z = acc[i][jj*4+2] + dv*wd4.z + bi4.z;
            o.w = acc[i][jj*4+3] + dv*wd4.w + bi4.w;
            *(float4*)(g_gates + rowb*G4_ + col) = o;
        }
    }
}

// ---------------- per-step: LSTM pointwise + h@WhrT + output + loss ----------------
// grid 128 blocks (8 rows each), 256 threads
__global__ __launch_bounds__(256) void k_post(const float* __restrict__ data,
                                              const float* __restrict__ masks,
                                              int s, float* __restrict__ out) {
    __shared__ float hs_s[8][H_];      // 16 KB
    __shared__ float Ws[32][128];      // 16 KB
    __shared__ float red[16];
    int rb = blockIdx.x;
    int tid = threadIdx.x;

    // phase 1: LSTM pointwise (8 rows x 512)
    #pragma unroll
    for (int t = 0; t < 16; t++) {
        int idx = tid + t*256;
        int r = idx >> 9, j = idx & 511;
        int b = rb*8 + r;
        int base = b*G4_ + j;
        float gi = g_gates[base];
        float gf = g_gates[base + H_];
        float gg = g_gates[base + 2*H_];
        float go = g_gates[base + 3*H_];
        float ig = 1.f/(1.f + expf(-gi));
        float fg = 1.f/(1.f + expf(-gf));
        float gt = tanhf(gg);
        float og = 1.f/(1.f + expf(-go));
        float cn = fg * g_c[b*H_ + j] + ig * gt;
        float hn = og * tanhf(cn);
        g_c[b*H_ + j] = cn;
        g_h[b*H_ + j] = hn;
        hs_s[r][j] = hn;
    }
    __syncthreads();

    // phase 2: 8x128 GEMM over K=512
    int r = tid >> 5;
    int c4 = (tid & 31) << 2;
    float4 acc = make_float4(0.f,0.f,0.f,0.f);
    for (int kc = 0; kc < H_; kc += 32) {
        #pragma unroll
        for (int i = 0; i < 4; i++) {
            int lidx = tid + i*256;
            int kr = lidx >> 5, cc = (lidx & 31) << 2;
            *(float4*)&Ws[kr][cc] = *(const float4*)(g_WhrT + (kc + kr)*D_ + cc);
        }
        __syncthreads();
        #pragma unroll 8
        for (int k = 0; k < 32; k++) {
            float a = hs_s[r][kc + k];
            float4 w = *(const float4*)&Ws[k][c4];
            acc.x = fmaf(a, w.x, acc.x);
            acc.y = fmaf(a, w.y, acc.y);
            acc.z = fmaf(a, w.z, acc.z);
            acc.w = fmaf(a, w.w, acc.w);
        }
        __syncthreads();
    }

    // epilogue: output combine + loss
    int b = rb*8 + r;
    int base = (b*S_ + s)*D_ + c4;
    float4 bh  = *(const float4*)(g_bhr + c4);
    float4 xv  = *(const float4*)(data + base);
    float4 mv  = *(const float4*)(masks + base);
    float4 xfv = *(const float4*)(g_xf + base);
    float4 xh2;
    xh2.x = acc.x + bh.x; xh2.y = acc.y + bh.y;
    xh2.z = acc.z + bh.z; xh2.w = acc.w + bh.w;
    float4 o;
    o.x = mv.x*xv.x + (1.f-mv.x)*(xh2.x + xfv.x);
    o.y = mv.y*xv.y + (1.f-mv.y)*(xh2.y + xfv.y);
    o.z = mv.z*xv.z + (1.f-mv.z)*(xh2.z + xfv.z);
    o.w = mv.w*xv.w + (1.f-mv.w)*(xh2.w + xfv.w);
    *(float4*)(out + base) = o;

    float ex = xv.x - xh2.x, ey = xv.y - xh2.y, ez = xv.z - xh2.z, ew = xv.w - xh2.w;
    float ln = mv.x*ex*ex + mv.y*ey*ey + mv.z*ez*ez + mv.w*ew*ew;
    float ld = mv.x + mv.y + mv.z + mv.w;
    #pragma unroll
    for (int off = 16; off > 0; off >>= 1) {
        ln += __shfl_down_sync(0xffffffffu, ln, off);
        ld += __shfl_down_sync(0xffffffffu, ld, off);
    }
    int warp = tid >> 5;
    if ((tid & 31) == 0) { red[2*warp] = ln; red[2*warp+1] = ld; }
    __syncthreads();
    if (tid == 0) {
        float a = 0.f, d2 = 0.f;
        #pragma unroll
        for (int w = 0; w < 8; w++) { a += red[2*w]; d2 += red[2*w+1]; }
        atomicAdd(&g_lnum[s], a);
        atomicAdd(&g_lden[s], d2);
    }
}

// ---------------- final loss ----------------
__global__ void k_loss(float* __restrict__ out, long long out_size) {
    __shared__ float sh[256];
    int t = threadIdx.x;
    sh[t] = g_lnum[t] / (g_lden[t] + 1e-5f);
    __syncthreads();
    for (int off = 128; off > 0; off >>= 1) {
        if (t < off) sh[t] += sh[t + off];
        __syncthreads();
    }
    if (t == 0 && out_size > (long long)B_*S_*D_)
        out[(long long)B_*S_*D_] = sh[0] / (float)S_;
}

// ---------------- launch ----------------
extern "C" void kernel_launch(void* const* d_in, const int* in_sizes, int n_in,
                              void* d_out, int out_size) {
    const float* data   = (const float*)d_in[0];
    const float* masks  = (const float*)d_in[1];
    const float* deltas = (const float*)d_in[2];
    const float* Wih    = (const float*)d_in[3];
    const float* Whh    = (const float*)d_in[4];
    const float* bih    = (const float*)d_in[5];
    const float* bhh    = (const float*)d_in[6];
    const float* Wtd    = (const float*)d_in[7];
    const float* btd    = (const float*)d_in[8];
    const float* Whr    = (const float*)d_in[9];
    const float* bhr    = (const float*)d_in[10];
    const float* Wfr    = (const float*)d_in[11];
    const float* bfr    = (const float*)d_in[12];
    float* out = (float*)d_out;

    k_init<<<1024, 256>>>();
    k_weights<<<2048, 256>>>(Wih, Whh, Whr, Wfr, bih, bhh, bhr);
    k_xf<<<(B_*S_)/32, 256>>>(data, bfr);

    for (int s = 0; s < S_; s++) {
        k_pre<<<128, 256>>>(data, masks, deltas, Wtd, btd, s);
        k_gates<<<dim3(G4_/128, B_/128), 256>>>(s, deltas, masks);
        k_post<<<128, 256>>>(data, masks, s, out);
    }
    k_loss<<<1, 256>>>(out, (long long)out_size);
}

// round 6
// speedup vs baseline: 1.7262x; 1.3710x over previous
#include <cuda_runtime.h>
#include <math.h>
#include <stdint.h>

#define B_ 1024
#define S_ 256
#define D_ 128
#define H_ 512
#define G4_ 2048   // 4*H

// ================= static device scratch =================
__device__ float g_h[B_*H_];
__device__ float g_c[B_*H_];
__device__ float g_hd[B_*H_];         // decayed h for current step
__device__ float g_xc[B_*D_];         // x_c for current step
__device__ float g_gates[B_*G4_];
__device__ float g_xf[B_*S_*D_];      // feat_reg(x) for all (b,s)
__device__ float g_Wg[G4_*768];       // K-major gates weight [n][k], tf32-rounded
__device__ float g_WhrT[H_*D_];       // k-major Whr
__device__ float g_WfrT[D_*D_];       // k-major Wfr
__device__ float g_wd[G4_];           // Wih[:,256] delta column (fp32)
__device__ float g_bias[G4_];         // bih + bhh (fp32)
__device__ float g_bhr[D_];
__device__ float g_lnum[S_];
__device__ float g_lden[S_];

__device__ __forceinline__ uint32_t f2tf32(float x) {
    uint32_t r; asm("cvt.rna.tf32.f32 %0, %1;" : "=r"(r) : "f"(x)); return r;
}

// ================= init =================
__global__ void k_init() {
    int n = 2*B_*H_ + 2*S_;
    for (int i = blockIdx.x*blockDim.x + threadIdx.x; i < n; i += gridDim.x*blockDim.x) {
        if (i < B_*H_) g_h[i] = 0.f;
        else if (i < 2*B_*H_) g_c[i - B_*H_] = 0.f;
        else {
            int j = i - 2*B_*H_;
            if (j < S_) g_lnum[j] = 0.f; else g_lden[j - S_] = 0.f;
        }
    }
}

// ================= build packed weights =================
__global__ void k_weights(const float* __restrict__ Wih, const float* __restrict__ Whh,
                          const float* __restrict__ Whr, const float* __restrict__ Wfr,
                          const float* __restrict__ bih, const float* __restrict__ bhh,
                          const float* __restrict__ bhr) {
    const int N1 = G4_*768;
    const int N2 = N1 + H_*D_;
    const int N3 = N2 + D_*D_;
    const int N4 = N3 + G4_;
    const int N5 = N4 + G4_;
    const int N6 = N5 + D_;
    for (int i = blockIdx.x*blockDim.x + threadIdx.x; i < N6; i += gridDim.x*blockDim.x) {
        if (i < N1) {
            int n = i / 768, k = i - n*768;
            float v = (k < 256) ? Wih[n*257 + k] : Whh[n*H_ + (k-256)];
            g_Wg[i] = __uint_as_float(f2tf32(v));
        } else if (i < N2) {
            int t = i - N1; int j = t >> 7, c = t & 127;
            g_WhrT[t] = Whr[c*H_ + j];
        } else if (i < N3) {
            int t = i - N2; int k = t >> 7, c = t & 127;
            g_WfrT[t] = Wfr[c*D_ + k];
        } else if (i < N4) {
            int g = i - N3;
            g_wd[g] = Wih[g*257 + 256];
        } else if (i < N5) {
            int g = i - N4;
            g_bias[g] = bih[g] + bhh[g];
        } else {
            int c = i - N5;
            g_bhr[c] = bhr[c];
        }
    }
}

// ================= precompute x_f for all (b,s) =================
__global__ __launch_bounds__(256) void k_xf(const float* __restrict__ data,
                                            const float* __restrict__ bfr) {
    __shared__ float xs[32][128];
    int row0 = blockIdx.x * 32;
    for (int idx = threadIdx.x; idx < 32*128; idx += 256)
        xs[idx >> 7][idx & 127] = data[row0*128 + idx];
    __syncthreads();

    int rg = threadIdx.x >> 5;
    int c  = (threadIdx.x & 31) << 2;
    float4 acc[4];
    #pragma unroll
    for (int rr = 0; rr < 4; rr++) acc[rr] = make_float4(0.f,0.f,0.f,0.f);

    #pragma unroll 4
    for (int k = 0; k < 128; k++) {
        float4 w = *(const float4*)(g_WfrT + k*D_ + c);
        #pragma unroll
        for (int rr = 0; rr < 4; rr++) {
            float a = xs[rg + rr*8][k];
            acc[rr].x = fmaf(a, w.x, acc[rr].x);
            acc[rr].y = fmaf(a, w.y, acc[rr].y);
            acc[rr].z = fmaf(a, w.z, acc[rr].z);
            acc[rr].w = fmaf(a, w.w, acc[rr].w);
        }
    }
    float4 bb = *(const float4*)(bfr + c);
    #pragma unroll
    for (int rr = 0; rr < 4; rr++) {
        int r = row0 + rg + rr*8;
        float4 o;
        o.x = acc[rr].x + bb.x; o.y = acc[rr].y + bb.y;
        o.z = acc[rr].z + bb.z; o.w = acc[rr].w + bb.w;
        *(float4*)(g_xf + r*D_ + c) = o;
    }
}

// ================= per-step: decay + hd@WhrT + x_c =================
// grid 128 blocks x 256 threads; block = 8 batch rows
__global__ __launch_bounds__(256) void k_pre(const float* __restrict__ data,
                                             const float* __restrict__ masks,
                                             const float* __restrict__ deltas,
                                             const float* __restrict__ Wtd,
                                             const float* __restrict__ btd, int s) {
    __shared__ float hd_s[8][H_];                  // 16 KB
    __shared__ __align__(16) float part[4][8][D_]; // 16 KB
    int rb = blockIdx.x, tid = threadIdx.x;

    // phase 1: decayed h
    #pragma unroll
    for (int t = 0; t < 16; t++) {
        int idx = tid + t*256;
        int r = idx >> 9, j = idx & 511;
        int b = rb*8 + r;
        float dv = deltas[b*S_ + s];
        float e = expf(-fmaxf(fmaf(dv, Wtd[j], btd[j]), 0.f));
        float v = g_h[b*H_ + j] * e;
        hd_s[r][j] = v;
        g_hd[b*H_ + j] = v;
    }
    __syncthreads();

    // phase 2: 4-way k-split, thread owns a float2 column pair for all 8 rows
    int ks = tid >> 6;
    int cg = tid & 63;
    float2 acc[8];
    #pragma unroll
    for (int r = 0; r < 8; r++) { acc[r].x = 0.f; acc[r].y = 0.f; }
    int k0 = ks * 128;
    #pragma unroll 4
    for (int k = k0; k < k0 + 128; k++) {
        float2 w = *(const float2*)(g_WhrT + k*D_ + cg*2);
        #pragma unroll
        for (int r = 0; r < 8; r++) {
            float a = hd_s[r][k];
            acc[r].x = fmaf(a, w.x, acc[r].x);
            acc[r].y = fmaf(a, w.y, acc[r].y);
        }
    }
    #pragma unroll
    for (int r = 0; r < 8; r++) *(float2*)&part[ks][r][cg*2] = acc[r];
    __syncthreads();

    // reduce partials + x_c epilogue
    #pragma unroll
    for (int i = 0; i < 2; i++) {
        int idx = tid + i*256;
        int r = idx >> 6, c2 = (idx & 63) * 2;
        float sx = part[0][r][c2]   + part[1][r][c2]   + part[2][r][c2]   + part[3][r][c2];
        float sy = part[0][r][c2+1] + part[1][r][c2+1] + part[2][r][c2+1] + part[3][r][c2+1];
        int b = rb*8 + r;
        int base = (b*S_ + s)*D_ + c2;
        float2 bh = *(const float2*)(g_bhr + c2);
        float2 xv = *(const float2*)(data + base);
        float2 mv = *(const float2*)(masks + base);
        float2 xc;
        xc.x = mv.x*xv.x + (1.f-mv.x)*(sx + bh.x);
        xc.y = mv.y*xv.y + (1.f-mv.y)*(sy + bh.y);
        *(float2*)(g_xc + b*D_ + c2) = xc;
    }
}

// ================= gates A loader (8 consecutive k at [row]) =================
__device__ __forceinline__ void fillA(int row, int k, int s,
                                      const float* __restrict__ masks,
                                      float4& lo, float4& hi) {
    if (k >= 256) {
        const float* p = g_hd + row*H_ + (k - 256);
        lo = *(const float4*)p;
        hi = *(const float4*)(p + 4);
    } else if (k >= 128) {
        const float* p = masks + (row*S_ + s)*D_ + (k - 128);
        lo = *(const float4*)p;
        hi = *(const float4*)(p + 4);
    } else {
        const float* p = g_xc + row*D_ + k;
        lo = *(const float4*)p;
        hi = *(const float4*)(p + 4);
    }
}

// Stage one K=32 chunk of A (128x32) and B (128x32) into smem in MMA FRAGMENT ORDER.
// A frag layout (m16n8k8 tf32, row-major A): float AF[8 m16][4 k8][32 lane][4 reg]
//   element (mr in 0..15, kc in 0..7): lane=((mr&7)<<2)|(kc&3), reg=((mr>>3)&1)|(((kc>>2)&1)<<1)
// B frag layout (col-major B): float BF[16 n8][4 k8][32 lane][2 reg]
//   element (n in 0..7, kc in 0..7): lane=((n&7)<<2)|(kc&3), reg=(kc>>2)&1
__device__ __forceinline__ void stage_chunk(int kbase, float* AF, float* BF,
                                            int bm, int bn, int s,
                                            const float* __restrict__ masks, int tid) {
    #pragma unroll
    for (int t = 0; t < 2; t++) {
        int idx = tid + t*256;          // 512 tasks: (row 0..127) x (kg 0..3)
        int row = idx >> 2;
        int kg = idx & 3;               // k8 index within chunk
        float4 lo, hi;
        fillA(bm + row, kbase + kg*8, s, masks, lo, hi);
        float f[8] = {lo.x, lo.y, lo.z, lo.w, hi.x, hi.y, hi.z, hi.w};
        int m16 = row >> 4, mr = row & 15;
        float* basep = AF + (m16*4 + kg)*128;
        #pragma unroll
        for (int e = 0; e < 8; e++) {
            int lane = ((mr & 7) << 2) | (e & 3);
            int reg  = ((mr >> 3) & 1) | (((e >> 2) & 1) << 1);
            basep[lane*4 + reg] = __uint_as_float(f2tf32(f[e]));
        }
    }
    #pragma unroll
    for (int t = 0; t < 2; t++) {
        int idx = tid + t*256;          // 512 tasks: (n 0..127) x (kg 0..3)
        int n = idx >> 2;
        int kg = idx & 3;
        const float* src = g_Wg + (size_t)(bn + n)*768 + kbase + kg*8;
        float4 lo = *(const float4*)src;
        float4 hi = *(const float4*)(src + 4);
        float f[8] = {lo.x, lo.y, lo.z, lo.w, hi.x, hi.y, hi.z, hi.w};
        int n8 = n >> 3, nr = n & 7;
        float* basep = BF + (n8*4 + kg)*64;
        #pragma unroll
        for (int e = 0; e < 8; e++) {
            int lane = (nr << 2) | (e & 3);
            int reg  = (e >> 2) & 1;
            basep[lane*2 + reg] = f[e];     // already tf32-rounded in g_Wg
        }
    }
}

// ================= per-step: gates GEMM via mma.sync tf32 =================
// grid (16 nb, 8 mb), 256 threads; CTA tile 128x128, K=768 in 24 chunks of 32
__global__ __launch_bounds__(256, 1) void k_gates(int s, const float* __restrict__ deltas,
                                                  const float* __restrict__ masks) {
    extern __shared__ float sm[];     // [2][A 4096 | B 4096] = 64 KB
    int tid = threadIdx.x;
    int wid = tid >> 5;
    int lane = tid & 31;
    int bm = blockIdx.y * 128;
    int bn = blockIdx.x * 128;
    int warp_m = wid >> 1;            // 0..3  (rows warp_m*32..+31)
    int warp_n = wid & 1;             // 0..1  (cols warp_n*64..+63)

    float acc[2][8][4];
    #pragma unroll
    for (int i = 0; i < 2; i++)
        #pragma unroll
        for (int j = 0; j < 8; j++)
            #pragma unroll
            for (int q = 0; q < 4; q++) acc[i][j][q] = 0.f;

    stage_chunk(0, sm, sm + 4096, bm, bn, s, masks, tid);
    __syncthreads();

    for (int c = 0; c < 24; c++) {
        int cb = c & 1;
        float* AF = sm + cb*8192;
        float* BF = AF + 4096;
        if (c < 23)
            stage_chunk((c+1)*32, sm + (cb^1)*8192, sm + (cb^1)*8192 + 4096, bm, bn, s, masks, tid);

        #pragma unroll
        for (int k8 = 0; k8 < 4; k8++) {
            uint32_t a[2][4];
            #pragma unroll
            for (int i = 0; i < 2; i++) {
                int m16 = warp_m*2 + i;
                float4 v = *(const float4*)(AF + (m16*4 + k8)*128 + lane*4);
                a[i][0] = __float_as_uint(v.x); a[i][1] = __float_as_uint(v.y);
                a[i][2] = __float_as_uint(v.z); a[i][3] = __float_as_uint(v.w);
            }
            #pragma unroll
            for (int j = 0; j < 8; j++) {
                int n8 = warp_n*8 + j;
                float2 bv = *(const float2*)(BF + (n8*4 + k8)*64 + lane*2);
                uint32_t b0 = __float_as_uint(bv.x), b1 = __float_as_uint(bv.y);
                #pragma unroll
                for (int i = 0; i < 2; i++) {
                    asm volatile(
                        "mma.sync.aligned.m16n8k8.row.col.f32.tf32.tf32.f32 "
                        "{%0,%1,%2,%3}, {%4,%5,%6,%7}, {%8,%9}, {%0,%1,%2,%3};\n"
                        : "+f"(acc[i][j][0]), "+f"(acc[i][j][1]),
                          "+f"(acc[i][j][2]), "+f"(acc[i][j][3])
                        : "r"(a[i][0]), "r"(a[i][1]), "r"(a[i][2]), "r"(a[i][3]),
                          "r"(b0), "r"(b1));
                }
            }
        }
        __syncthreads();
    }

    // epilogue: acc(m16n8): c0,c1 at (g, 2t),(g, 2t+1); c2,c3 at (g+8, ...)
    int g = lane >> 2, tc = lane & 3;
    #pragma unroll
    for (int i = 0; i < 2; i++) {
        int row0 = bm + warp_m*32 + i*16 + g;
        float dv0 = deltas[row0*S_ + s];
        float dv1 = deltas[(row0+8)*S_ + s];
        #pragma unroll
        for (int j = 0; j < 8; j++) {
            int col = bn + warp_n*64 + j*8 + tc*2;
            float2 wd2 = *(const float2*)(g_wd + col);
            float2 bi2 = *(const float2*)(g_bias + col);
            float2 o0, o1;
            o0.x = acc[i][j][0] + dv0*wd2.x + bi2.x;
            o0.y = acc[i][j][1] + dv0*wd2.y + bi2.y;
            o1.x = acc[i][j][2] + dv1*wd2.x + bi2.x;
            o1.y = acc[i][j][3] + dv1*wd2.y + bi2.y;
            *(float2*)(g_gates + (size_t)row0*G4_ + col) = o0;
            *(float2*)(g_gates + (size_t)(row0+8)*G4_ + col) = o1;
        }
    }
}

// ================= per-step: LSTM pointwise + h@WhrT + output + loss =================
__global__ __launch_bounds__(256) void k_post(const float* __restrict__ data,
                                              const float* __restrict__ masks,
                                              int s, float* __restrict__ out) {
    __shared__ float hs_s[8][H_];
    __shared__ __align__(16) float part[4][8][D_];
    __shared__ float red[16];
    int rb = blockIdx.x, tid = threadIdx.x;

    // phase 1: LSTM pointwise
    #pragma unroll
    for (int t = 0; t < 16; t++) {
        int idx = tid + t*256;
        int r = idx >> 9, j = idx & 511;
        int b = rb*8 + r;
        size_t base = (size_t)b*G4_ + j;
        float gi = g_gates[base];
        float gf = g_gates[base + H_];
        float gg = g_gates[base + 2*H_];
        float go = g_gates[base + 3*H_];
        float ig = 1.f/(1.f + expf(-gi));
        float fg = 1.f/(1.f + expf(-gf));
        float gt = tanhf(gg);
        float og = 1.f/(1.f + expf(-go));
        float cn = fg * g_c[b*H_ + j] + ig * gt;
        float hn = og * tanhf(cn);
        g_c[b*H_ + j] = cn;
        g_h[b*H_ + j] = hn;
        hs_s[r][j] = hn;
    }
    __syncthreads();

    // phase 2: 4-way k-split GEMM
    int ks = tid >> 6;
    int cg = tid & 63;
    float2 acc[8];
    #pragma unroll
    for (int r = 0; r < 8; r++) { acc[r].x = 0.f; acc[r].y = 0.f; }
    int k0 = ks * 128;
    #pragma unroll 4
    for (int k = k0; k < k0 + 128; k++) {
        float2 w = *(const float2*)(g_WhrT + k*D_ + cg*2);
        #pragma unroll
        for (int r = 0; r < 8; r++) {
            float a = hs_s[r][k];
            acc[r].x = fmaf(a, w.x, acc[r].x);
            acc[r].y = fmaf(a, w.y, acc[r].y);
        }
    }
    #pragma unroll
    for (int r = 0; r < 8; r++) *(float2*)&part[ks][r][cg*2] = acc[r];
    __syncthreads();

    // reduce + output combine + loss
    float ln = 0.f, ld = 0.f;
    #pragma unroll
    for (int i = 0; i < 2; i++) {
        int idx = tid + i*256;
        int r = idx >> 6, c2 = (idx & 63) * 2;
        float sx = part[0][r][c2]   + part[1][r][c2]   + part[2][r][c2]   + part[3][r][c2];
        float sy = part[0][r][c2+1] + part[1][r][c2+1] + part[2][r][c2+1] + part[3][r][c2+1];
        int b = rb*8 + r;
        int base = (b*S_ + s)*D_ + c2;
        float2 bh  = *(const float2*)(g_bhr + c2);
        float2 xv  = *(const float2*)(data + base);
        float2 mv  = *(const float2*)(masks + base);
        float2 xfv = *(const float2*)(g_xf + base);
        float xh2x = sx + bh.x, xh2y = sy + bh.y;
        float2 o;
        o.x = mv.x*xv.x + (1.f-mv.x)*(xh2x + xfv.x);
        o.y = mv.y*xv.y + (1.f-mv.y)*(xh2y + xfv.y);
        *(float2*)(out + base) = o;
        float ex = xv.x - xh2x, ey = xv.y - xh2y;
        ln += mv.x*ex*ex + mv.y*ey*ey;
        ld += mv.x + mv.y;
    }
    #pragma unroll
    for (int off = 16; off > 0; off >>= 1) {
        ln += __shfl_down_sync(0xffffffffu, ln, off);
        ld += __shfl_down_sync(0xffffffffu, ld, off);
    }
    int warp = tid >> 5;
    if ((tid & 31) == 0) { red[2*warp] = ln; red[2*warp+1] = ld; }
    __syncthreads();
    if (tid == 0) {
        float a = 0.f, d2 = 0.f;
        #pragma unroll
        for (int w = 0; w < 8; w++) { a += red[2*w]; d2 += red[2*w+1]; }
        atomicAdd(&g_lnum[s], a);
        atomicAdd(&g_lden[s], d2);
    }
}

// ================= final loss =================
__global__ void k_loss(float* __restrict__ out, long long out_size) {
    __shared__ float sh[256];
    int t = threadIdx.x;
    sh[t] = g_lnum[t] / (g_lden[t] + 1e-5f);
    __syncthreads();
    for (int off = 128; off > 0; off >>= 1) {
        if (t < off) sh[t] += sh[t + off];
        __syncthreads();
    }
    if (t == 0 && out_size > (long long)B_*S_*D_)
        out[(long long)B_*S_*D_] = sh[0] / (float)S_;
}

// ================= launch =================
extern "C" void kernel_launch(void* const* d_in, const int* in_sizes, int n_in,
                              void* d_out, int out_size) {
    const float* data   = (const float*)d_in[0];
    const float* masks  = (const float*)d_in[1];
    const float* deltas = (const float*)d_in[2];
    const float* Wih    = (const float*)d_in[3];
    const float* Whh    = (const float*)d_in[4];
    const float* bih    = (const float*)d_in[5];
    const float* bhh    = (const float*)d_in[6];
    const float* Wtd    = (const float*)d_in[7];
    const float* btd    = (const float*)d_in[8];
    const float* Whr    = (const float*)d_in[9];
    const float* bhr    = (const float*)d_in[10];
    const float* Wfr    = (const float*)d_in[11];
    const float* bfr    = (const float*)d_in[12];
    float* out = (float*)d_out;

    const int GATES_SMEM = 2 * 8192 * 4;   // 64 KB
    cudaFuncSetAttribute(k_gates, cudaFuncAttributeMaxDynamicSharedMemorySize, GATES_SMEM);

    k_init<<<1024, 256>>>();
    k_weights<<<2048, 256>>>(Wih, Whh, Whr, Wfr, bih, bhh, bhr);
    k_xf<<<(B_*S_)/32, 256>>>(data, bfr);

    for (int s = 0; s < S_; s++) {
        k_pre<<<128, 256>>>(data, masks, deltas, Wtd, btd, s);
        k_gates<<<dim3(16, 8), 256, GATES_SMEM>>>(s, deltas, masks);
        k_post<<<128, 256>>>(data, masks, s, out);
    }
    k_loss<<<1, 256>>>(out, (long long)out_size);
}

// round 7
// speedup vs baseline: 2.7502x; 1.5932x over previous
#include <cuda_runtime.h>
#include <math.h>
#include <stdint.h>

#define B_ 1024
#define S_ 256
#define D_ 128
#define H_ 512
#define G4_ 2048   // 4*H

// ================= static device scratch =================
__device__ float g_h[B_*H_];
__device__ float g_c[B_*H_];
__device__ float g_gates[B_*G4_];
__device__ float g_xf[B_*S_*D_];      // feat_reg(x) for all (b,s)
__device__ float g_AF[64*96*128];     // A panel in mma-fragment order [m16][k8][128]
__device__ float g_WgF[256*96*64];    // B weights in mma-fragment order [n8][k8][64]
__device__ float g_WhrT[H_*D_];       // k-major Whr
__device__ float g_WfrT[D_*D_];       // k-major Wfr
__device__ float g_wd[G4_];           // Wih[:,256] delta column (fp32)
__device__ float g_bias[G4_];         // bih + bhh (fp32)
__device__ float g_bhr[D_];
__device__ float g_lnum[S_];
__device__ float g_lden[S_];

__device__ __forceinline__ uint32_t f2tf32(float x) {
    uint32_t r; asm("cvt.rna.tf32.f32 %0, %1;" : "=r"(r) : "f"(x)); return r;
}
__device__ __forceinline__ float tanh_fast(float x) {
    float r; asm("tanh.approx.f32 %0, %1;" : "=f"(r) : "f"(x)); return r;
}
__device__ __forceinline__ float sig_fast(float x) {
    return __fdividef(1.f, 1.f + __expf(-x));
}

// fragment address helpers (m16n8k8: A row-major frag, B col-major frag)
__device__ __forceinline__ int a_frag_off(int row, int k) {
    int m16 = row >> 4, mr = row & 15;
    int k8 = k >> 3, kc = k & 7;
    int lane = ((mr & 7) << 2) | (kc & 3);
    int reg  = ((mr >> 3) & 1) | (((kc >> 2) & 1) << 1);
    return (m16*96 + k8)*128 + lane*4 + reg;
}

// ================= init =================
__global__ void k_init() {
    int n = 2*B_*H_ + 2*S_;
    for (int i = blockIdx.x*blockDim.x + threadIdx.x; i < n; i += gridDim.x*blockDim.x) {
        if (i < B_*H_) g_h[i] = 0.f;
        else if (i < 2*B_*H_) g_c[i - B_*H_] = 0.f;
        else {
            int j = i - 2*B_*H_;
            if (j < S_) g_lnum[j] = 0.f; else g_lden[j - S_] = 0.f;
        }
    }
}

// ================= build packed weights =================
__global__ void k_weights(const float* __restrict__ Wih, const float* __restrict__ Whh,
                          const float* __restrict__ Whr, const float* __restrict__ Wfr,
                          const float* __restrict__ bih, const float* __restrict__ bhh,
                          const float* __restrict__ bhr) {
    const int N1 = G4_*768;
    const int N2 = N1 + H_*D_;
    const int N3 = N2 + D_*D_;
    const int N4 = N3 + G4_;
    const int N5 = N4 + G4_;
    const int N6 = N5 + D_;
    for (int i = blockIdx.x*blockDim.x + threadIdx.x; i < N6; i += gridDim.x*blockDim.x) {
        if (i < N1) {
            int n = i / 768, k = i - n*768;
            float v = (k < 256) ? Wih[n*257 + k] : Whh[n*H_ + (k-256)];
            int n8 = n >> 3, nr = n & 7, k8 = k >> 3, kc = k & 7;
            int pos = (n8*96 + k8)*64 + (((nr << 2) | (kc & 3)) << 1) + (kc >> 2);
            g_WgF[pos] = __uint_as_float(f2tf32(v));
        } else if (i < N2) {
            int t = i - N1; int j = t >> 7, c = t & 127;
            g_WhrT[t] = Whr[c*H_ + j];
        } else if (i < N3) {
            int t = i - N2; int k = t >> 7, c = t & 127;
            g_WfrT[t] = Wfr[c*D_ + k];
        } else if (i < N4) {
            int g = i - N3;
            g_wd[g] = Wih[g*257 + 256];
        } else if (i < N5) {
            int g = i - N4;
            g_bias[g] = bih[g] + bhh[g];
        } else {
            int c = i - N5;
            g_bhr[c] = bhr[c];
        }
    }
}

// ================= precompute x_f for all (b,s) =================
__global__ __launch_bounds__(256) void k_xf(const float* __restrict__ data,
                                            const float* __restrict__ bfr) {
    __shared__ float xs[32][128];
    int row0 = blockIdx.x * 32;
    for (int idx = threadIdx.x; idx < 32*128; idx += 256)
        xs[idx >> 7][idx & 127] = data[row0*128 + idx];
    __syncthreads();

    int rg = threadIdx.x >> 5;
    int c  = (threadIdx.x & 31) << 2;
    float4 acc[4];
    #pragma unroll
    for (int rr = 0; rr < 4; rr++) acc[rr] = make_float4(0.f,0.f,0.f,0.f);

    #pragma unroll 4
    for (int k = 0; k < 128; k++) {
        float4 w = *(const float4*)(g_WfrT + k*D_ + c);
        #pragma unroll
        for (int rr = 0; rr < 4; rr++) {
            float a = xs[rg + rr*8][k];
            acc[rr].x = fmaf(a, w.x, acc[rr].x);
            acc[rr].y = fmaf(a, w.y, acc[rr].y);
            acc[rr].z = fmaf(a, w.z, acc[rr].z);
            acc[rr].w = fmaf(a, w.w, acc[rr].w);
        }
    }
    float4 bb = *(const float4*)(bfr + c);
    #pragma unroll
    for (int rr = 0; rr < 4; rr++) {
        int r = row0 + rg + rr*8;
        float4 o;
        o.x = acc[rr].x + bb.x; o.y = acc[rr].y + bb.y;
        o.z = acc[rr].z + bb.z; o.w = acc[rr].w + bb.w;
        *(float4*)(g_xf + r*D_ + c) = o;
    }
}

// ================= per-step: decay + hd@WhrT + A-panel fragments =================
// grid 128 blocks x 512 threads; block = 8 batch rows
__global__ __launch_bounds__(512) void k_pre(const float* __restrict__ data,
                                             const float* __restrict__ masks,
                                             const float* __restrict__ deltas,
                                             const float* __restrict__ Wtd,
                                             const float* __restrict__ btd, int s) {
    __shared__ __align__(16) float hd_s[8][H_];    // 16 KB
    __shared__ __align__(16) float part[4][8][D_]; // 16 KB
    int rb = blockIdx.x, tid = threadIdx.x;

    // phase 1: decayed h + hd fragments (k = 256 + j)
    #pragma unroll
    for (int t = 0; t < 8; t++) {
        int idx = tid + t*512;
        int r = idx >> 9, j = idx & 511;
        int row = rb*8 + r;
        float dv = deltas[row*S_ + s];
        float e = __expf(-fmaxf(fmaf(dv, Wtd[j], btd[j]), 0.f));
        float v = g_h[row*H_ + j] * e;
        hd_s[r][j] = v;
        g_AF[a_frag_off(row, 256 + j)] = __uint_as_float(f2tf32(v));
    }
    __syncthreads();

    // phase 2: x_h partial GEMM, 4-way k-split x 128 cols
    int ks = tid >> 7;          // 0..3
    int c  = tid & 127;         // column
    float acc[8];
    #pragma unroll
    for (int r = 0; r < 8; r++) acc[r] = 0.f;
    int k0 = ks * 128;
    #pragma unroll 2
    for (int kb = k0; kb < k0 + 128; kb += 4) {
        float w0 = g_WhrT[(kb+0)*D_ + c];
        float w1 = g_WhrT[(kb+1)*D_ + c];
        float w2 = g_WhrT[(kb+2)*D_ + c];
        float w3 = g_WhrT[(kb+3)*D_ + c];
        #pragma unroll
        for (int r = 0; r < 8; r++) {
            float4 hv = *(const float4*)&hd_s[r][kb];
            acc[r] = fmaf(hv.x, w0, acc[r]);
            acc[r] = fmaf(hv.y, w1, acc[r]);
            acc[r] = fmaf(hv.z, w2, acc[r]);
            acc[r] = fmaf(hv.w, w3, acc[r]);
        }
    }
    #pragma unroll
    for (int r = 0; r < 8; r++) part[ks][r][c] = acc[r];
    __syncthreads();

    // epilogue: x_c + mask fragments (1024 outputs, 2 per thread)
    #pragma unroll
    for (int t = 0; t < 2; t++) {
        int idx = tid + t*512;
        int r = idx >> 7, cc = idx & 127;
        float xh = part[0][r][cc] + part[1][r][cc] + part[2][r][cc] + part[3][r][cc] + g_bhr[cc];
        int row = rb*8 + r;
        int gbase = (row*S_ + s)*D_ + cc;
        float xv = data[gbase], mv = masks[gbase];
        float xc = mv*xv + (1.f - mv)*xh;
        g_AF[a_frag_off(row, cc)]       = __uint_as_float(f2tf32(xc));
        g_AF[a_frag_off(row, 128 + cc)] = mv;   // 0/1 exact in tf32
    }
}

// ================= gates: stage one K=32 chunk (pure vectorized copy) =================
__device__ __forceinline__ void stage_copy(int c, float* AF, float* BF,
                                           int m16b, int n8b, int tid) {
    #pragma unroll
    for (int t = 0; t < 4; t++) {
        int g = tid + t*256;
        int frag = g >> 5;             // 0..31 (8 m16 x 4 k8)
        int part = g & 31;
        int m16l = frag >> 2, k8l = frag & 3;
        const float4 v = *(const float4*)(g_AF + ((size_t)(m16b + m16l)*96 + c*4 + k8l)*128 + part*4);
        *(float4*)(AF + (m16l*4 + k8l)*128 + part*4) = v;
    }
    #pragma unroll
    for (int t = 0; t < 4; t++) {
        int g = tid + t*256;
        int frag = g >> 4;             // 0..63 (16 n8 x 4 k8)
        int part = g & 15;
        int n8l = frag >> 2, k8l = frag & 3;
        const float4 v = *(const float4*)(g_WgF + ((size_t)(n8b + n8l)*96 + c*4 + k8l)*64 + part*4);
        *(float4*)(BF + (n8l*4 + k8l)*64 + part*4) = v;
    }
}

// ================= per-step: gates GEMM via mma.sync tf32 =================
// grid (16 nb, 8 mb), 256 threads; CTA tile 128x128, K=768 in 24 chunks of 32
__global__ __launch_bounds__(256, 1) void k_gates(int s, const float* __restrict__ deltas) {
    extern __shared__ float sm[];     // [2][A 4096 | B 4096] = 64 KB
    int tid = threadIdx.x;
    int wid = tid >> 5;
    int lane = tid & 31;
    int bm = blockIdx.y * 128;
    int bn = blockIdx.x * 128;
    int m16b = blockIdx.y * 8;
    int n8b = blockIdx.x * 16;
    int warp_m = wid >> 1;            // 0..3
    int warp_n = wid & 1;             // 0..1

    float acc[2][8][4];
    #pragma unroll
    for (int i = 0; i < 2; i++)
        #pragma unroll
        for (int j = 0; j < 8; j++)
            #pragma unroll
            for (int q = 0; q < 4; q++) acc[i][j][q] = 0.f;

    stage_copy(0, sm, sm + 4096, m16b, n8b, tid);
    __syncthreads();

    for (int c = 0; c < 24; c++) {
        int cb = c & 1;
        float* AF = sm + cb*8192;
        float* BF = AF + 4096;
        if (c < 23)
            stage_copy(c+1, sm + (cb^1)*8192, sm + (cb^1)*8192 + 4096, m16b, n8b, tid);

        #pragma unroll
        for (int k8 = 0; k8 < 4; k8++) {
            uint32_t a[2][4];
            #pragma unroll
            for (int i = 0; i < 2; i++) {
                int m16 = warp_m*2 + i;
                float4 v = *(const float4*)(AF + (m16*4 + k8)*128 + lane*4);
                a[i][0] = __float_as_uint(v.x); a[i][1] = __float_as_uint(v.y);
                a[i][2] = __float_as_uint(v.z); a[i][3] = __float_as_uint(v.w);
            }
            #pragma unroll
            for (int j = 0; j < 8; j++) {
                int n8 = warp_n*8 + j;
                float2 bv = *(const float2*)(BF + (n8*4 + k8)*64 + lane*2);
                uint32_t b0 = __float_as_uint(bv.x), b1 = __float_as_uint(bv.y);
                #pragma unroll
                for (int i = 0; i < 2; i++) {
                    asm volatile(
                        "mma.sync.aligned.m16n8k8.row.col.f32.tf32.tf32.f32 "
                        "{%0,%1,%2,%3}, {%4,%5,%6,%7}, {%8,%9}, {%0,%1,%2,%3};\n"
                        : "+f"(acc[i][j][0]), "+f"(acc[i][j][1]),
                          "+f"(acc[i][j][2]), "+f"(acc[i][j][3])
                        : "r"(a[i][0]), "r"(a[i][1]), "r"(a[i][2]), "r"(a[i][3]),
                          "r"(b0), "r"(b1));
                }
            }
        }
        __syncthreads();
    }

    // epilogue
    int g = lane >> 2, tc = lane & 3;
    #pragma unroll
    for (int i = 0; i < 2; i++) {
        int row0 = bm + warp_m*32 + i*16 + g;
        float dv0 = deltas[row0*S_ + s];
        float dv1 = deltas[(row0+8)*S_ + s];
        #pragma unroll
        for (int j = 0; j < 8; j++) {
            int col = bn + warp_n*64 + j*8 + tc*2;
            float2 wd2 = *(const float2*)(g_wd + col);
            float2 bi2 = *(const float2*)(g_bias + col);
            float2 o0, o1;
            o0.x = acc[i][j][0] + dv0*wd2.x + bi2.x;
            o0.y = acc[i][j][1] + dv0*wd2.y + bi2.y;
            o1.x = acc[i][j][2] + dv1*wd2.x + bi2.x;
            o1.y = acc[i][j][3] + dv1*wd2.y + bi2.y;
            *(float2*)(g_gates + (size_t)row0*G4_ + col) = o0;
            *(float2*)(g_gates + (size_t)(row0+8)*G4_ + col) = o1;
        }
    }
}

// ================= per-step: LSTM pointwise + h@WhrT + output + loss =================
// grid 128 blocks x 512 threads
__global__ __launch_bounds__(512) void k_post(const float* __restrict__ data,
                                              const float* __restrict__ masks,
                                              int s, float* __restrict__ out) {
    __shared__ __align__(16) float hs_s[8][H_];
    __shared__ __align__(16) float part[4][8][D_];
    __shared__ float red[32];
    int rb = blockIdx.x, tid = threadIdx.x;

    // phase 1: LSTM pointwise
    #pragma unroll
    for (int t = 0; t < 8; t++) {
        int idx = tid + t*512;
        int r = idx >> 9, j = idx & 511;
        int row = rb*8 + r;
        size_t base = (size_t)row*G4_ + j;
        float gi = g_gates[base];
        float gf = g_gates[base + H_];
        float gg = g_gates[base + 2*H_];
        float go = g_gates[base + 3*H_];
        float ig = sig_fast(gi);
        float fg = sig_fast(gf);
        float gt = tanh_fast(gg);
        float og = sig_fast(go);
        float cn = fg * g_c[row*H_ + j] + ig * gt;
        float hn = og * tanh_fast(cn);
        g_c[row*H_ + j] = cn;
        g_h[row*H_ + j] = hn;
        hs_s[r][j] = hn;
    }
    __syncthreads();

    // phase 2: x_h2 partial GEMM
    int ks = tid >> 7;
    int c  = tid & 127;
    float acc[8];
    #pragma unroll
    for (int r = 0; r < 8; r++) acc[r] = 0.f;
    int k0 = ks * 128;
    #pragma unroll 2
    for (int kb = k0; kb < k0 + 128; kb += 4) {
        float w0 = g_WhrT[(kb+0)*D_ + c];
        float w1 = g_WhrT[(kb+1)*D_ + c];
        float w2 = g_WhrT[(kb+2)*D_ + c];
        float w3 = g_WhrT[(kb+3)*D_ + c];
        #pragma unroll
        for (int r = 0; r < 8; r++) {
            float4 hv = *(const float4*)&hs_s[r][kb];
            acc[r] = fmaf(hv.x, w0, acc[r]);
            acc[r] = fmaf(hv.y, w1, acc[r]);
            acc[r] = fmaf(hv.z, w2, acc[r]);
            acc[r] = fmaf(hv.w, w3, acc[r]);
        }
    }
    #pragma unroll
    for (int r = 0; r < 8; r++) part[ks][r][c] = acc[r];
    __syncthreads();

    // epilogue: combine + loss
    float ln = 0.f, ld = 0.f;
    #pragma unroll
    for (int t = 0; t < 2; t++) {
        int idx = tid + t*512;
        int r = idx >> 7, cc = idx & 127;
        float xh2 = part[0][r][cc] + part[1][r][cc] + part[2][r][cc] + part[3][r][cc] + g_bhr[cc];
        int row = rb*8 + r;
        int gbase = (row*S_ + s)*D_ + cc;
        float xv = data[gbase], mv = masks[gbase];
        float xfv = g_xf[gbase];
        out[gbase] = mv*xv + (1.f - mv)*(xh2 + xfv);
        float ex = xv - xh2;
        ln += mv*ex*ex;
        ld += mv;
    }
    #pragma unroll
    for (int off = 16; off > 0; off >>= 1) {
        ln += __shfl_down_sync(0xffffffffu, ln, off);
        ld += __shfl_down_sync(0xffffffffu, ld, off);
    }
    int warp = tid >> 5;
    if ((tid & 31) == 0) { red[2*warp] = ln; red[2*warp+1] = ld; }
    __syncthreads();
    if (tid == 0) {
        float a = 0.f, d2 = 0.f;
        #pragma unroll
        for (int w = 0; w < 16; w++) { a += red[2*w]; d2 += red[2*w+1]; }
        atomicAdd(&g_lnum[s], a);
        atomicAdd(&g_lden[s], d2);
    }
}

// ================= final loss =================
__global__ void k_loss(float* __restrict__ out, long long out_size) {
    __shared__ float sh[256];
    int t = threadIdx.x;
    sh[t] = g_lnum[t] / (g_lden[t] + 1e-5f);
    __syncthreads();
    for (int off = 128; off > 0; off >>= 1) {
        if (t < off) sh[t] += sh[t + off];
        __syncthreads();
    }
    if (t == 0 && out_size > (long long)B_*S_*D_)
        out[(long long)B_*S_*D_] = sh[0] / (float)S_;
}

// ================= launch =================
extern "C" void kernel_launch(void* const* d_in, const int* in_sizes, int n_in,
                              void* d_out, int out_size) {
    const float* data   = (const float*)d_in[0];
    const float* masks  = (const float*)d_in[1];
    const float* deltas = (const float*)d_in[2];
    const float* Wih    = (const float*)d_in[3];
    const float* Whh    = (const float*)d_in[4];
    const float* bih    = (const float*)d_in[5];
    const float* bhh    = (const float*)d_in[6];
    const float* Wtd    = (const float*)d_in[7];
    const float* btd    = (const float*)d_in[8];
    const float* Whr    = (const float*)d_in[9];
    const float* bhr    = (const float*)d_in[10];
    const float* Wfr    = (const float*)d_in[11];
    const float* bfr    = (const float*)d_in[12];
    float* out = (float*)d_out;

    const int GATES_SMEM = 2 * 8192 * 4;   // 64 KB
    cudaFuncSetAttribute(k_gates, cudaFuncAttributeMaxDynamicSharedMemorySize, GATES_SMEM);

    k_init<<<1024, 256>>>();
    k_weights<<<2048, 256>>>(Wih, Whh, Whr, Wfr, bih, bhh, bhr);
    k_xf<<<(B_*S_)/32, 256>>>(data, bfr);

    for (int s = 0; s < S_; s++) {
        k_pre<<<128, 512>>>(data, masks, deltas, Wtd, btd, s);
        k_gates<<<dim3(16, 8), 256, GATES_SMEM>>>(s, deltas);
        k_post<<<128, 512>>>(data, masks, s, out);
    }
    k_loss<<<1, 256>>>(out, (long long)out_size);
}

// round 8
// speedup vs baseline: 3.1152x; 1.1327x over previous
#include <cuda_runtime.h>
#include <math.h>
#include <stdint.h>

#define B_ 1024
#define S_ 256
#define D_ 128
#define H_ 512
#define G4_ 2048   // 4*H

// ================= static device scratch =================
__device__ float g_c[B_*H_];
__device__ float g_gates[B_*G4_];
__device__ float g_xf[B_*S_*D_];      // feat_reg(x) for all (b,s)
__device__ float g_AF[64*96*128];     // A panel in mma-fragment order [m16][k8][128]
__device__ float g_WgF[256*96*64];    // B weights in mma-fragment order [n8][k8][64]
__device__ float g_WhrT[H_*D_];       // k-major Whr
__device__ float g_WfrT[D_*D_];       // k-major Wfr
__device__ float g_wd[G4_];           // Wih[:,256] delta column (fp32)
__device__ float g_bias[G4_];         // bih + bhh (fp32)
__device__ float g_bhr[D_];
__device__ float g_lnum[S_];
__device__ float g_lden[S_];

__device__ __forceinline__ uint32_t f2tf32(float x) {
    uint32_t r; asm("cvt.rna.tf32.f32 %0, %1;" : "=r"(r) : "f"(x)); return r;
}
__device__ __forceinline__ float tanh_fast(float x) {
    float r; asm("tanh.approx.f32 %0, %1;" : "=f"(r) : "f"(x)); return r;
}
__device__ __forceinline__ float sig_fast(float x) {
    return __fdividef(1.f, 1.f + __expf(-x));
}

// fragment address (m16n8k8 tf32, row-major A)
__device__ __forceinline__ int a_frag_off(int row, int k) {
    int m16 = row >> 4, mr = row & 15;
    int k8 = k >> 3, kc = k & 7;
    int lane = ((mr & 7) << 2) | (kc & 3);
    int reg  = ((mr >> 3) & 1) | (((kc >> 2) & 1) << 1);
    return (m16*96 + k8)*128 + lane*4 + reg;
}

// ================= init =================
__global__ void k_init() {
    int n = B_*H_ + 2*S_;
    for (int i = blockIdx.x*blockDim.x + threadIdx.x; i < n; i += gridDim.x*blockDim.x) {
        if (i < B_*H_) g_c[i] = 0.f;
        else {
            int j = i - B_*H_;
            if (j < S_) g_lnum[j] = 0.f; else g_lden[j - S_] = 0.f;
        }
    }
}

// ================= build packed weights =================
__global__ void k_weights(const float* __restrict__ Wih, const float* __restrict__ Whh,
                          const float* __restrict__ Whr, const float* __restrict__ Wfr,
                          const float* __restrict__ bih, const float* __restrict__ bhh,
                          const float* __restrict__ bhr) {
    const int N1 = G4_*768;
    const int N2 = N1 + H_*D_;
    const int N3 = N2 + D_*D_;
    const int N4 = N3 + G4_;
    const int N5 = N4 + G4_;
    const int N6 = N5 + D_;
    for (int i = blockIdx.x*blockDim.x + threadIdx.x; i < N6; i += gridDim.x*blockDim.x) {
        if (i < N1) {
            int n = i / 768, k = i - n*768;
            float v = (k < 256) ? Wih[n*257 + k] : Whh[n*H_ + (k-256)];
            int n8 = n >> 3, nr = n & 7, k8 = k >> 3, kc = k & 7;
            int pos = (n8*96 + k8)*64 + (((nr << 2) | (kc & 3)) << 1) + (kc >> 2);
            g_WgF[pos] = __uint_as_float(f2tf32(v));
        } else if (i < N2) {
            int t = i - N1; int j = t >> 7, c = t & 127;
            g_WhrT[t] = Whr[c*H_ + j];
        } else if (i < N3) {
            int t = i - N2; int k = t >> 7, c = t & 127;
            g_WfrT[t] = Wfr[c*D_ + k];
        } else if (i < N4) {
            int g = i - N3;
            g_wd[g] = Wih[g*257 + 256];
        } else if (i < N5) {
            int g = i - N4;
            g_bias[g] = bih[g] + bhh[g];
        } else {
            int c = i - N5;
            g_bhr[c] = bhr[c];
        }
    }
}

// ================= precompute x_f for all (b,s) =================
__global__ __launch_bounds__(256) void k_xf(const float* __restrict__ data,
                                            const float* __restrict__ bfr) {
    __shared__ float xs[32][128];
    int row0 = blockIdx.x * 32;
    for (int idx = threadIdx.x; idx < 32*128; idx += 256)
        xs[idx >> 7][idx & 127] = data[row0*128 + idx];
    __syncthreads();

    int rg = threadIdx.x >> 5;
    int c  = (threadIdx.x & 31) << 2;
    float4 acc[4];
    #pragma unroll
    for (int rr = 0; rr < 4; rr++) acc[rr] = make_float4(0.f,0.f,0.f,0.f);

    #pragma unroll 4
    for (int k = 0; k < 128; k++) {
        float4 w = *(const float4*)(g_WfrT + k*D_ + c);
        #pragma unroll
        for (int rr = 0; rr < 4; rr++) {
            float a = xs[rg + rr*8][k];
            acc[rr].x = fmaf(a, w.x, acc[rr].x);
            acc[rr].y = fmaf(a, w.y, acc[rr].y);
            acc[rr].z = fmaf(a, w.z, acc[rr].z);
            acc[rr].w = fmaf(a, w.w, acc[rr].w);
        }
    }
    float4 bb = *(const float4*)(bfr + c);
    #pragma unroll
    for (int rr = 0; rr < 4; rr++) {
        int r = row0 + rg + rr*8;
        float4 o;
        o.x = acc[rr].x + bb.x; o.y = acc[rr].y + bb.y;
        o.z = acc[rr].z + bb.z; o.w = acc[rr].w + bb.w;
        *(float4*)(g_xf + r*D_ + c) = o;
    }
}

// ================= one-time A-panel init for s=0 (h=0 => x_h=bhr, hd=0) ==========
__global__ __launch_bounds__(256) void k_pre0(const float* __restrict__ data,
                                              const float* __restrict__ masks) {
    int i = blockIdx.x*blockDim.x + threadIdx.x;   // 0 .. 1024*768-1
    if (i >= B_*768) return;
    int row = i / 768;
    int k = i - row*768;
    float v;
    if (k < 128) {
        int gbase = row*S_*D_ + k;     // s = 0
        float xv = data[gbase], mv = masks[gbase];
        v = mv*xv + (1.f - mv)*g_bhr[k];
    } else if (k < 256) {
        v = masks[row*S_*D_ + (k - 128)];
    } else {
        v = 0.f;
    }
    g_AF[a_frag_off(row, k)] = __uint_as_float(f2tf32(v));
}

// ================= gates: stage one K=32 chunk (pure vectorized copy) =================
__device__ __forceinline__ void stage_copy(int c, float* AF, float* BF,
                                           int m16b, int n8b, int tid) {
    #pragma unroll
    for (int t = 0; t < 4; t++) {
        int g = tid + t*256;
        int frag = g >> 5;             // 0..31 (8 m16 x 4 k8)
        int part = g & 31;
        int m16l = frag >> 2, k8l = frag & 3;
        const float4 v = *(const float4*)(g_AF + ((size_t)(m16b + m16l)*96 + c*4 + k8l)*128 + part*4);
        *(float4*)(AF + (m16l*4 + k8l)*128 + part*4) = v;
    }
    #pragma unroll
    for (int t = 0; t < 4; t++) {
        int g = tid + t*256;
        int frag = g >> 4;             // 0..63 (16 n8 x 4 k8)
        int part = g & 15;
        int n8l = frag >> 2, k8l = frag & 3;
        const float4 v = *(const float4*)(g_WgF + ((size_t)(n8b + n8l)*96 + c*4 + k8l)*64 + part*4);
        *(float4*)(BF + (n8l*4 + k8l)*64 + part*4) = v;
    }
}

// ================= per-step: gates GEMM via mma.sync tf32 =================
// grid (16 nb, 8 mb), 256 threads; CTA tile 128x128, K=768 in 24 chunks of 32
__global__ __launch_bounds__(256, 1) void k_gates(int s, const float* __restrict__ deltas) {
    extern __shared__ float sm[];     // [2][A 4096 | B 4096] = 64 KB
    int tid = threadIdx.x;
    int wid = tid >> 5;
    int lane = tid & 31;
    int bm = blockIdx.y * 128;
    int bn = blockIdx.x * 128;
    int m16b = blockIdx.y * 8;
    int n8b = blockIdx.x * 16;
    int warp_m = wid >> 1;            // 0..3
    int warp_n = wid & 1;             // 0..1

    float acc[2][8][4];
    #pragma unroll
    for (int i = 0; i < 2; i++)
        #pragma unroll
        for (int j = 0; j < 8; j++)
            #pragma unroll
            for (int q = 0; q < 4; q++) acc[i][j][q] = 0.f;

    stage_copy(0, sm, sm + 4096, m16b, n8b, tid);
    __syncthreads();

    for (int c = 0; c < 24; c++) {
        int cb = c & 1;
        float* AF = sm + cb*8192;
        float* BF = AF + 4096;
        if (c < 23)
            stage_copy(c+1, sm + (cb^1)*8192, sm + (cb^1)*8192 + 4096, m16b, n8b, tid);

        #pragma unroll
        for (int k8 = 0; k8 < 4; k8++) {
            uint32_t a[2][4];
            #pragma unroll
            for (int i = 0; i < 2; i++) {
                int m16 = warp_m*2 + i;
                float4 v = *(const float4*)(AF + (m16*4 + k8)*128 + lane*4);
                a[i][0] = __float_as_uint(v.x); a[i][1] = __float_as_uint(v.y);
                a[i][2] = __float_as_uint(v.z); a[i][3] = __float_as_uint(v.w);
            }
            #pragma unroll
            for (int j = 0; j < 8; j++) {
                int n8 = warp_n*8 + j;
                float2 bv = *(const float2*)(BF + (n8*4 + k8)*64 + lane*2);
                uint32_t b0 = __float_as_uint(bv.x), b1 = __float_as_uint(bv.y);
                #pragma unroll
                for (int i = 0; i < 2; i++) {
                    asm volatile(
                        "mma.sync.aligned.m16n8k8.row.col.f32.tf32.tf32.f32 "
                        "{%0,%1,%2,%3}, {%4,%5,%6,%7}, {%8,%9}, {%0,%1,%2,%3};\n"
                        : "+f"(acc[i][j][0]), "+f"(acc[i][j][1]),
                          "+f"(acc[i][j][2]), "+f"(acc[i][j][3])
                        : "r"(a[i][0]), "r"(a[i][1]), "r"(a[i][2]), "r"(a[i][3]),
                          "r"(b0), "r"(b1));
                }
            }
        }
        __syncthreads();
    }

    // epilogue
    int g = lane >> 2, tc = lane & 3;
    #pragma unroll
    for (int i = 0; i < 2; i++) {
        int row0 = bm + warp_m*32 + i*16 + g;
        float dv0 = deltas[row0*S_ + s];
        float dv1 = deltas[(row0+8)*S_ + s];
        #pragma unroll
        for (int j = 0; j < 8; j++) {
            int col = bn + warp_n*64 + j*8 + tc*2;
            float2 wd2 = *(const float2*)(g_wd + col);
            float2 bi2 = *(const float2*)(g_bias + col);
            float2 o0, o1;
            o0.x = acc[i][j][0] + dv0*wd2.x + bi2.x;
            o0.y = acc[i][j][1] + dv0*wd2.y + bi2.y;
            o1.x = acc[i][j][2] + dv1*wd2.x + bi2.x;
            o1.y = acc[i][j][3] + dv1*wd2.y + bi2.y;
            *(float2*)(g_gates + (size_t)row0*G4_ + col) = o0;
            *(float2*)(g_gates + (size_t)(row0+8)*G4_ + col) = o1;
        }
    }
}

// ===== per-step fused: LSTM pointwise + BOTH small GEMMs + out/loss + next-step A panel =====
// grid 128 blocks x 1024 threads; block = 8 batch rows
__global__ __launch_bounds__(1024, 1) void k_post(const float* __restrict__ data,
                                                  const float* __restrict__ masks,
                                                  const float* __restrict__ deltas,
                                                  const float* __restrict__ Wtd,
                                                  const float* __restrict__ btd,
                                                  int s, float* __restrict__ out) {
    extern __shared__ float smp[];
    float* hs_s = smp;            // 8*512 (h_new)
    float* hd_s = smp + 4096;     // 8*512 (decayed h for s+1)
    float* ph   = smp + 8192;     // [4 ks][8 r][128 c] partials (h path)
    float* pd   = smp + 12288;    // [4 ks][8 r][128 c] partials (hd path)
    __shared__ float red[64];
    int rb = blockIdx.x, tid = threadIdx.x;
    const bool has_next = (s + 1 < S_);

    // phase 1: LSTM pointwise + decay for s+1 + hd fragments
    #pragma unroll
    for (int t = 0; t < 4; t++) {
        int idx = tid + t*1024;
        int r = idx >> 9, j = idx & 511;
        int row = rb*8 + r;
        size_t base = (size_t)row*G4_ + j;
        float gi = g_gates[base];
        float gf = g_gates[base + H_];
        float gg = g_gates[base + 2*H_];
        float go = g_gates[base + 3*H_];
        float cn = sig_fast(gf)*g_c[row*H_ + j] + sig_fast(gi)*tanh_fast(gg);
        float hn = sig_fast(go)*tanh_fast(cn);
        g_c[row*H_ + j] = cn;
        hs_s[r*512 + j] = hn;
        float v = 0.f;
        if (has_next) {
            float dv = deltas[row*S_ + s + 1];
            float e = __expf(-fmaxf(fmaf(dv, Wtd[j], btd[j]), 0.f));
            v = hn * e;
            g_AF[a_frag_off(row, 256 + j)] = __uint_as_float(f2tf32(v));
        }
        hd_s[r*512 + j] = v;
    }
    __syncthreads();

    // phase 2: dual GEMM (h@WhrT and hd@WhrT share W loads)
    // thread -> (rs 0..1, ks 0..3, c 0..127)
    int rs = tid >> 9;
    int ks = (tid >> 7) & 3;
    int c  = tid & 127;
    float acc_h[4] = {0.f,0.f,0.f,0.f};
    float acc_d[4] = {0.f,0.f,0.f,0.f};
    int k0 = ks*128;
    #pragma unroll 2
    for (int kb = k0; kb < k0 + 128; kb += 4) {
        float w0 = g_WhrT[(kb+0)*D_ + c];
        float w1 = g_WhrT[(kb+1)*D_ + c];
        float w2 = g_WhrT[(kb+2)*D_ + c];
        float w3 = g_WhrT[(kb+3)*D_ + c];
        #pragma unroll
        for (int r = 0; r < 4; r++) {
            int rr = rs*4 + r;
            float4 ha = *(const float4*)&hs_s[rr*512 + kb];
            float4 hb = *(const float4*)&hd_s[rr*512 + kb];
            acc_h[r] = fmaf(ha.x, w0, acc_h[r]);
            acc_h[r] = fmaf(ha.y, w1, acc_h[r]);
            acc_h[r] = fmaf(ha.z, w2, acc_h[r]);
            acc_h[r] = fmaf(ha.w, w3, acc_h[r]);
            acc_d[r] = fmaf(hb.x, w0, acc_d[r]);
            acc_d[r] = fmaf(hb.y, w1, acc_d[r]);
            acc_d[r] = fmaf(hb.z, w2, acc_d[r]);
            acc_d[r] = fmaf(hb.w, w3, acc_d[r]);
        }
    }
    #pragma unroll
    for (int r = 0; r < 4; r++) {
        ph[(ks*8 + rs*4 + r)*128 + c] = acc_h[r];
        pd[(ks*8 + rs*4 + r)*128 + c] = acc_d[r];
    }
    __syncthreads();

    // epilogue: one (r, c) output per thread
    int r = tid >> 7, cc = tid & 127;
    int row = rb*8 + r;
    float bh = g_bhr[cc];
    float ln, ld;
    {
        float xh2 = ph[(0*8+r)*128+cc] + ph[(1*8+r)*128+cc]
                  + ph[(2*8+r)*128+cc] + ph[(3*8+r)*128+cc] + bh;
        int gbase = (row*S_ + s)*D_ + cc;
        float xv = data[gbase], mv = masks[gbase];
        float xfv = g_xf[gbase];
        out[gbase] = mv*xv + (1.f - mv)*(xh2 + xfv);
        float ex = xv - xh2;
        ln = mv*ex*ex;
        ld = mv;
    }
    if (has_next) {
        float xh = pd[(0*8+r)*128+cc] + pd[(1*8+r)*128+cc]
                 + pd[(2*8+r)*128+cc] + pd[(3*8+r)*128+cc] + bh;
        int gb2 = (row*S_ + s + 1)*D_ + cc;
        float xv = data[gb2], mv = masks[gb2];
        float xc = mv*xv + (1.f - mv)*xh;
        g_AF[a_frag_off(row, cc)]       = __uint_as_float(f2tf32(xc));
        g_AF[a_frag_off(row, 128 + cc)] = mv;
    }

    // loss reduce
    #pragma unroll
    for (int off = 16; off > 0; off >>= 1) {
        ln += __shfl_down_sync(0xffffffffu, ln, off);
        ld += __shfl_down_sync(0xffffffffu, ld, off);
    }
    int warp = tid >> 5;
    if ((tid & 31) == 0) { red[2*warp] = ln; red[2*warp+1] = ld; }
    __syncthreads();
    if (tid == 0) {
        float a = 0.f, d2 = 0.f;
        #pragma unroll
        for (int w = 0; w < 32; w++) { a += red[2*w]; d2 += red[2*w+1]; }
        atomicAdd(&g_lnum[s], a);
        atomicAdd(&g_lden[s], d2);
    }
}

// ================= final loss =================
__global__ void k_loss(float* __restrict__ out, long long out_size) {
    __shared__ float sh[256];
    int t = threadIdx.x;
    sh[t] = g_lnum[t] / (g_lden[t] + 1e-5f);
    __syncthreads();
    for (int off = 128; off > 0; off >>= 1) {
        if (t < off) sh[t] += sh[t + off];
        __syncthreads();
    }
    if (t == 0 && out_size > (long long)B_*S_*D_)
        out[(long long)B_*S_*D_] = sh[0] / (float)S_;
}

// ================= launch =================
extern "C" void kernel_launch(void* const* d_in, const int* in_sizes, int n_in,
                              void* d_out, int out_size) {
    const float* data   = (const float*)d_in[0];
    const float* masks  = (const float*)d_in[1];
    const float* deltas = (const float*)d_in[2];
    const float* Wih    = (const float*)d_in[3];
    const float* Whh    = (const float*)d_in[4];
    const float* bih    = (const float*)d_in[5];
    const float* bhh    = (const float*)d_in[6];
    const float* Wtd    = (const float*)d_in[7];
    const float* btd    = (const float*)d_in[8];
    const float* Whr    = (const float*)d_in[9];
    const float* bhr    = (const float*)d_in[10];
    const float* Wfr    = (const float*)d_in[11];
    const float* bfr    = (const float*)d_in[12];
    float* out = (float*)d_out;

    const int GATES_SMEM = 2 * 8192 * 4;    // 64 KB
    const int POST_SMEM  = 16384 * 4;       // 64 KB
    cudaFuncSetAttribute(k_gates, cudaFuncAttributeMaxDynamicSharedMemorySize, GATES_SMEM);
    cudaFuncSetAttribute(k_post,  cudaFuncAttributeMaxDynamicSharedMemorySize, POST_SMEM);

    k_init<<<1024, 256>>>();
    k_weights<<<2048, 256>>>(Wih, Whh, Whr, Wfr, bih, bhh, bhr);
    k_xf<<<(B_*S_)/32, 256>>>(data, bfr);
    k_pre0<<<(B_*768 + 255)/256, 256>>>(data, masks);

    for (int s = 0; s < S_; s++) {
        k_gates<<<dim3(16, 8), 256, GATES_SMEM>>>(s, deltas);
        k_post<<<128, 1024, POST_SMEM>>>(data, masks, deltas, Wtd, btd, s, out);
    }
    k_loss<<<1, 256>>>(out, (long long)out_size);
}